// round 5
// baseline (speedup 1.0000x reference)
#include <cuda_runtime.h>
#include <cstdint>

// ---------------- problem constants ----------------
#define BATCH 2
#define C3 256
#define HW 48           // lv3 spatial
#define M48 (HW*HW)     // 2304 patch positions
#define HP 50           // padded 48+2
#define NP 2500         // 50*50
#define NPS 2560        // padded GEMM dim (20 * 128)
#define KTILE 16
#define NKSTEPS 16      // 256 / 16
#define STAGES 4

// ---------------- scratch (device globals; no runtime alloc) ----------------
__device__ __align__(16) float g_lrp[BATCH * C3 * NPS];        // padded lr  [b][c][u]
__device__ __align__(16) float g_rfp[BATCH * C3 * NPS];        // padded refsr
__device__ __align__(16) float g_E[(size_t)BATCH * NPS * NPS]; // E[b][i][j]
__device__ __align__(16) float g_D[(size_t)BATCH * M48 * M48]; // D[b][m][l]
__device__ float g_SS[2 * BATCH * NP];
__device__ float g_invn[2 * BATCH * M48];
__device__ int   g_Hidx[BATCH * M48];
__device__ int   g_src[3 * BATCH * M48];

// ---------------- prep: zero-padded images ----------------
__global__ void prep_kernel(const float* __restrict__ lr, const float* __restrict__ refsr) {
    int t = blockIdx.x * blockDim.x + threadIdx.x;
    if (t >= 2 * BATCH * C3 * NPS) return;
    int u = t % NPS; int r = t / NPS;
    int c = r % C3; r /= C3;
    int b = r & 1; int which = r >> 1;
    float val = 0.f;
    if (u < NP) {
        int rr = u / HP, cc = u % HP;
        if (rr >= 1 && rr < 49 && cc >= 1 && cc < 49) {
            const float* src = which ? refsr : lr;
            val = src[((size_t)(b * C3 + c)) * M48 + (rr - 1) * HW + (cc - 1)];
        }
    }
    float* dst = which ? g_rfp : g_lrp;
    dst[((size_t)(b * C3 + c)) * NPS + u] = val;
}

// ---------------- per-pixel channel sum of squares ----------------
__global__ void ssq_kernel() {
    int t = blockIdx.x * blockDim.x + threadIdx.x;
    if (t >= 2 * BATCH * NP) return;
    int u = t % NP; int b = (t / NP) & 1; int which = t / (BATCH * NP);
    const float* src = (which ? g_rfp : g_lrp) + (size_t)b * C3 * NPS + u;
    float acc = 0.f;
#pragma unroll 8
    for (int c = 0; c < C3; c++) { float x = src[(size_t)c * NPS]; acc += x * x; }
    g_SS[t] = acc;
}

// ---------------- patch inverse norms ----------------
__global__ void norm_kernel() {
    int t = blockIdx.x * blockDim.x + threadIdx.x;
    if (t >= 2 * BATCH * M48) return;
    int m = t % M48; int b = (t / M48) & 1; int which = t / (BATCH * M48);
    int mi = m / HW, mj = m % HW;
    const float* S = g_SS + (which * BATCH + b) * NP;
    float s = 0.f;
#pragma unroll
    for (int di = 0; di < 3; di++)
#pragma unroll
        for (int dj = 0; dj < 3; dj++)
            s += S[(mi + di) * HP + mj + dj];
    g_invn[t] = 1.0f / fmaxf(sqrtf(s), 1e-12f);
}

// ---------------- SGEMM: E = lrp^T * rfp (2560x2560, K=256), FFMA2 + 4-stage cp.async ----------------
__global__ void __launch_bounds__(256) gemm_kernel() {
    int b = blockIdx.z;
    const float* A = g_lrp + (size_t)b * C3 * NPS;
    const float* B = g_rfp + (size_t)b * C3 * NPS;
    float* C = g_E + (size_t)b * NPS * NPS;

    __shared__ __align__(16) float As[STAGES][KTILE][128];
    __shared__ __align__(16) float Bs[STAGES][KTILE][128];

    int tid = threadIdx.x;
    int iBase = blockIdx.x * 128;
    int jBase = blockIdx.y * 128;
    int lk = tid >> 5;          // 0..7  (rows lk and lk+8)
    int lc = (tid & 31) << 2;   // 0..124
    const float* Aptr = A + (size_t)lk * NPS + iBase + lc;
    const float* Bptr = B + (size_t)lk * NPS + jBase + lc;

#define ISSUE(stage, kt) do {                                                          \
        uint32_t sa0 = (uint32_t)__cvta_generic_to_shared(&As[(stage)][lk][lc]);       \
        uint32_t sa1 = (uint32_t)__cvta_generic_to_shared(&As[(stage)][lk + 8][lc]);   \
        uint32_t sb0 = (uint32_t)__cvta_generic_to_shared(&Bs[(stage)][lk][lc]);       \
        uint32_t sb1 = (uint32_t)__cvta_generic_to_shared(&Bs[(stage)][lk + 8][lc]);   \
        const float* ga0 = Aptr + (size_t)(kt) * KTILE * NPS;                          \
        const float* ga1 = ga0 + (size_t)8 * NPS;                                      \
        const float* gb0 = Bptr + (size_t)(kt) * KTILE * NPS;                          \
        const float* gb1 = gb0 + (size_t)8 * NPS;                                      \
        asm volatile("cp.async.ca.shared.global [%0], [%1], 16;\n" :: "r"(sa0), "l"(ga0)); \
        asm volatile("cp.async.ca.shared.global [%0], [%1], 16;\n" :: "r"(sa1), "l"(ga1)); \
        asm volatile("cp.async.ca.shared.global [%0], [%1], 16;\n" :: "r"(sb0), "l"(gb0)); \
        asm volatile("cp.async.ca.shared.global [%0], [%1], 16;\n" :: "r"(sb1), "l"(gb1)); \
        asm volatile("cp.async.commit_group;\n" ::: "memory");                         \
    } while (0)

    ISSUE(0, 0);
    ISSUE(1, 1);
    ISSUE(2, 2);

    int ty = tid >> 4, tx = tid & 15;   // 16x16 thread grid

    unsigned long long accp[8][4];
#pragma unroll
    for (int i = 0; i < 8; i++)
#pragma unroll
        for (int j = 0; j < 4; j++) accp[i][j] = 0ull;

    for (int kt = 0; kt < NKSTEPS; kt++) {
        asm volatile("cp.async.wait_group 2;\n" ::: "memory");
        __syncthreads();
        if (kt + 3 < NKSTEPS) { int st = (kt + 3) % STAGES; ISSUE(st, kt + 3); }
        int cur = kt % STAGES;
#pragma unroll
        for (int kk = 0; kk < KTILE; kk++) {
            float4 a0 = *(float4*)&As[cur][kk][ty * 4];
            float4 a1 = *(float4*)&As[cur][kk][64 + ty * 4];
            unsigned long long bp[4];
            *(ulonglong2*)(bp)     = *(ulonglong2*)&Bs[cur][kk][tx * 4];
            *(ulonglong2*)(bp + 2) = *(ulonglong2*)&Bs[cur][kk][64 + tx * 4];
            float ar[8] = {a0.x, a0.y, a0.z, a0.w, a1.x, a1.y, a1.z, a1.w};
#pragma unroll
            for (int i = 0; i < 8; i++) {
                unsigned long long a2;
                asm("mov.b64 %0, {%1, %1};" : "=l"(a2) : "r"(__float_as_uint(ar[i])));
#pragma unroll
                for (int jp = 0; jp < 4; jp++) {
                    asm("fma.rn.f32x2 %0, %1, %2, %0;"
                        : "+l"(accp[i][jp]) : "l"(a2), "l"(bp[jp]));
                }
            }
        }
    }

#pragma unroll
    for (int half = 0; half < 2; half++) {
#pragma unroll
        for (int ii = 0; ii < 4; ii++) {
            int i = half * 4 + ii;
            int row = iBase + half * 64 + ty * 4 + ii;
            float* crow = C + (size_t)row * NPS + jBase;
            *(ulonglong2*)(crow + tx * 4)      = make_ulonglong2(accp[i][0], accp[i][1]);
            *(ulonglong2*)(crow + 64 + tx * 4) = make_ulonglong2(accp[i][2], accp[i][3]);
        }
    }
#undef ISSUE
}

// ---------------- aggregate 9 E-taps -> D row, plus argmax over keys ----------------
__global__ void __launch_bounds__(256) agg_kernel() {
    int m = blockIdx.x, b = blockIdx.y;
    int mi = m / HW, mj = m % HW;
    const float* Eb = g_E + (size_t)b * NPS * NPS;
    float inq = g_invn[(0 * BATCH + b) * M48 + m];
    const float* invk = g_invn + (1 * BATCH + b) * M48;
    float* Drow = g_D + ((size_t)b * M48 + m) * M48;

    const float* base0 = Eb + (size_t)((mi + 0) * HP + mj) * NPS + 0 * HP;
    const float* base1 = Eb + (size_t)((mi + 1) * HP + mj) * NPS + 1 * HP;
    const float* base2 = Eb + (size_t)((mi + 2) * HP + mj) * NPS + 2 * HP;

    float bv = -1e30f; int bi = 1 << 30;
    for (int l = threadIdx.x; l < M48; l += 256) {
        int li = l / HW, lj = l % HW;
        int o = li * HP + lj;
        float s = base0[o] + base0[o + NPS + 1] + base0[o + 2 * NPS + 2]
                + base1[o] + base1[o + NPS + 1] + base1[o + 2 * NPS + 2]
                + base2[o] + base2[o + NPS + 1] + base2[o + 2 * NPS + 2];
        float val = s * inq * invk[l];
        Drow[l] = val;
        if (val > bv) { bv = val; bi = l; }
    }
    // warp shuffle argmax (tie -> min index)
#pragma unroll
    for (int off = 16; off; off >>= 1) {
        float v2 = __shfl_down_sync(0xffffffffu, bv, off);
        int   i2 = __shfl_down_sync(0xffffffffu, bi, off);
        if (v2 > bv || (v2 == bv && i2 < bi)) { bv = v2; bi = i2; }
    }
    __shared__ float sv[8];
    __shared__ int   si[8];
    if ((threadIdx.x & 31) == 0) { sv[threadIdx.x >> 5] = bv; si[threadIdx.x >> 5] = bi; }
    __syncthreads();
    if (threadIdx.x == 0) {
        float v0 = sv[0]; int i0 = si[0];
#pragma unroll
        for (int w = 1; w < 8; w++) {
            if (sv[w] > v0 || (sv[w] == v0 && si[w] < i0)) { v0 = sv[w]; i0 = si[w]; }
        }
        g_Hidx[b * M48 + m] = i0;
    }
}

// ---------------- single-pass stable top-3 of D[m][Hidx[j]] over j ----------------
__device__ __forceinline__ void ins3(float v, int j,
                                     float& v0, int& i0, float& v1, int& i1, float& v2, int& i2) {
    bool b2 = (v > v2) || (v == v2 && j < i2);
    if (b2) {
        bool b1 = (v > v1) || (v == v1 && j < i1);
        if (b1) {
            bool b0 = (v > v0) || (v == v0 && j < i0);
            if (b0) { v2 = v1; i2 = i1; v1 = v0; i1 = i0; v0 = v; i0 = j; }
            else    { v2 = v1; i2 = i1; v1 = v;  i1 = j; }
        } else      { v2 = v;  i2 = j; }
    }
}

__global__ void __launch_bounds__(256) topk_kernel(float* __restrict__ outS) {
    int m = blockIdx.x, b = blockIdx.y;
    __shared__ float rowv[M48];
    __shared__ int   hs[M48];
    const float* Drow = g_D + ((size_t)b * M48 + m) * M48;
    for (int j = threadIdx.x; j < M48; j += 256) {
        rowv[j] = Drow[j];
        hs[j] = g_Hidx[b * M48 + j];
    }
    __syncthreads();

    float v0 = -1e30f, v1 = -1e30f, v2 = -1e30f;
    int   i0 = 1 << 30, i1 = 1 << 30, i2 = 1 << 30;
    for (int j = threadIdx.x; j < M48; j += 256) {
        ins3(rowv[hs[j]], j, v0, i0, v1, i1, v2, i2);
    }
    // warp tournament: merge triples via shuffles
#pragma unroll
    for (int off = 16; off; off >>= 1) {
        float w0 = __shfl_down_sync(0xffffffffu, v0, off);
        float w1 = __shfl_down_sync(0xffffffffu, v1, off);
        float w2 = __shfl_down_sync(0xffffffffu, v2, off);
        int   a0 = __shfl_down_sync(0xffffffffu, i0, off);
        int   a1 = __shfl_down_sync(0xffffffffu, i1, off);
        int   a2 = __shfl_down_sync(0xffffffffu, i2, off);
        ins3(w0, a0, v0, i0, v1, i1, v2, i2);
        ins3(w1, a1, v0, i0, v1, i1, v2, i2);
        ins3(w2, a2, v0, i0, v1, i1, v2, i2);
    }
    __shared__ float wv[8][3];
    __shared__ int   wi[8][3];
    if ((threadIdx.x & 31) == 0) {
        int w = threadIdx.x >> 5;
        wv[w][0] = v0; wv[w][1] = v1; wv[w][2] = v2;
        wi[w][0] = i0; wi[w][1] = i1; wi[w][2] = i2;
    }
    __syncthreads();
    if (threadIdx.x == 0) {
        float r0 = wv[0][0], r1 = wv[0][1], r2 = wv[0][2];
        int   s0 = wi[0][0], s1 = wi[0][1], s2 = wi[0][2];
#pragma unroll
        for (int w = 1; w < 8; w++) {
            ins3(wv[w][0], wi[w][0], r0, s0, r1, s1, r2, s2);
            ins3(wv[w][1], wi[w][1], r0, s0, r1, s1, r2, s2);
            ins3(wv[w][2], wi[w][2], r0, s0, r1, s1, r2, s2);
        }
        outS[(0 * BATCH + b) * M48 + m] = r0;
        outS[(1 * BATCH + b) * M48 + m] = r1;
        outS[(2 * BATCH + b) * M48 + m] = r2;
        g_src[(0 * BATCH + b) * M48 + m] = hs[s0];
        g_src[(1 * BATCH + b) * M48 + m] = hs[s1];
        g_src[(2 * BATCH + b) * M48 + m] = hs[s2];
    }
}

// ---------------- transfer: fold(gather(unfold(ref))) / 9, any pyramid level ----------------
__global__ void transfer_kernel(const float* __restrict__ ref, float* __restrict__ out,
                                int R, int C, int S, int CCH) {
    int t = blockIdx.x * blockDim.x + threadIdx.x;
    int nCh = C / CCH;
    int total = 3 * BATCH * nCh * S * S;
    if (t >= total) return;
    int x = t % S; int tmp = t / S;
    int y = tmp % S; tmp /= S;
    int cc = tmp % nCh; tmp /= nCh;
    int b = tmp & 1; int i = tmp >> 1;

    const int* srcTab = g_src + (i * BATCH + b) * M48;
    int yp = y + R, xp = x + R;
    int v = yp - 3 * R + 1; int milo = (v <= 0) ? 0 : (v + R - 1) / R;
    int mihi = yp / R; if (mihi > 47) mihi = 47;
    v = xp - 3 * R + 1; int mjlo = (v <= 0) ? 0 : (v + R - 1) / R;
    int mjhi = xp / R; if (mjhi > 47) mjhi = 47;

    float mk[9]; int off[9];
#pragma unroll
    for (int a = 0; a < 3; a++) {
        int mi = milo + a;
#pragma unroll
        for (int e = 0; e < 3; e++) {
            int mj = mjlo + e;
            int u = a * 3 + e;
            mk[u] = 0.f; off[u] = 0;
            if (mi <= mihi && mj <= mjhi) {
                int s = srcTab[mi * HW + mj];
                int smi = s / HW, smj = s % HW;
                int ry = y + (smi - mi) * R;
                int rx = x + (smj - mj) * R;
                if (ry >= 0 && ry < S && rx >= 0 && rx < S) { off[u] = ry * S + rx; mk[u] = 1.0f; }
            }
        }
    }
    int c0 = cc * CCH;
    const float* refb = ref + ((size_t)(b * C + c0)) * S * S;
    float* outb = out + ((size_t)((i * BATCH + b) * C + c0)) * S * S + y * S + x;
    for (int c = 0; c < CCH; c++) {
        const float* rc = refb + (size_t)c * S * S;
        float acc = 0.f;
#pragma unroll
        for (int u = 0; u < 9; u++) acc += mk[u] * __ldg(rc + off[u]);
        outb[(size_t)c * S * S] = acc * (1.0f / 9.0f);
    }
}

// ---------------- launch ----------------
extern "C" void kernel_launch(void* const* d_in, const int* in_sizes, int n_in,
                              void* d_out, int out_size) {
    const float* lr    = (const float*)d_in[0];
    const float* refsr = (const float*)d_in[1];
    const float* ref1  = (const float*)d_in[2];  // (2,64,192,192)
    const float* ref2  = (const float*)d_in[3];  // (2,128,96,96)
    const float* ref3  = (const float*)d_in[4];  // (2,256,48,48)
    float* out = (float*)d_out;

    float* outS  = out;
    float* outT3 = outS + 3 * BATCH * M48;
    float* outT2 = outT3 + 3 * BATCH * C3 * M48;
    float* outT1 = outT2 + 3 * BATCH * 128 * 96 * 96;

    {
        int n = 2 * BATCH * C3 * NPS;
        prep_kernel<<<(n + 255) / 256, 256>>>(lr, refsr);
    }
    ssq_kernel<<<(2 * BATCH * NP + 255) / 256, 256>>>();
    norm_kernel<<<(2 * BATCH * M48 + 255) / 256, 256>>>();
    gemm_kernel<<<dim3(20, 20, BATCH), 256>>>();
    agg_kernel<<<dim3(M48, BATCH), 256>>>();
    topk_kernel<<<dim3(M48, BATCH), 256>>>(outS);

    {   // lv3: R=1, C=256, S=48, CCH=32
        int n = 3 * BATCH * (C3 / 32) * 48 * 48;
        transfer_kernel<<<(n + 255) / 256, 256>>>(ref3, outT3, 1, 256, 48, 32);
    }
    {   // lv2: R=2, C=128, S=96, CCH=32
        int n = 3 * BATCH * (128 / 32) * 96 * 96;
        transfer_kernel<<<(n + 255) / 256, 256>>>(ref2, outT2, 2, 128, 96, 32);
    }
    {   // lv1: R=4, C=64, S=192, CCH=32
        int n = 3 * BATCH * (64 / 32) * 192 * 192;
        transfer_kernel<<<(n + 255) / 256, 256>>>(ref1, outT1, 4, 64, 192, 32);
    }
}

// round 6
// speedup vs baseline: 1.0573x; 1.0573x over previous
#include <cuda_runtime.h>
#include <cstdint>

// ---------------- problem constants ----------------
#define BATCH 2
#define C3 256
#define HW 48           // lv3 spatial
#define M48 (HW*HW)     // 2304 patch positions
#define HP 50           // padded 48+2
#define NP 2500         // 50*50
#define NPS 2560        // padded GEMM dim (20 * 128)
#define KTILE 32
#define NKSTEPS 8       // 256 / 32
#define STAGES 3
#define GEMM_SMEM (STAGES * KTILE * 128 * 2 * 4)   // 98304 bytes

// table sizes: plane-major per level, 9 planes of (6*S*S)
#define NPL3 (6 * 48 * 48)      // 13824
#define NPL2 (6 * 96 * 96)      // 55296
#define NPL1 (6 * 192 * 192)    // 221184
#define TOFS3 0
#define TOFS2 (9 * NPL3)                 // 124416
#define TOFS1 (TOFS2 + 9 * NPL2)         // 622080
#define TTOT  (TOFS1 + 9 * NPL1)         // 2612736

// ---------------- scratch (device globals; no runtime alloc) ----------------
__device__ __align__(16) float g_lrp[BATCH * C3 * NPS];
__device__ __align__(16) float g_rfp[BATCH * C3 * NPS];
__device__ __align__(16) float g_E[(size_t)BATCH * NPS * NPS];
__device__ __align__(16) float g_D[(size_t)BATCH * M48 * M48];
__device__ float g_SS[2 * BATCH * NP];
__device__ float g_invn[2 * BATCH * M48];
__device__ int   g_Hidx[BATCH * M48];
__device__ int   g_src[3 * BATCH * M48];
__device__ int   g_toff[TTOT];
__device__ float g_tw[TTOT];

// ---------------- prep: zero-padded images ----------------
__global__ void prep_kernel(const float* __restrict__ lr, const float* __restrict__ refsr) {
    int t = blockIdx.x * blockDim.x + threadIdx.x;
    if (t >= 2 * BATCH * C3 * NPS) return;
    int u = t % NPS; int r = t / NPS;
    int c = r % C3; r /= C3;
    int b = r & 1; int which = r >> 1;
    float val = 0.f;
    if (u < NP) {
        int rr = u / HP, cc = u % HP;
        if (rr >= 1 && rr < 49 && cc >= 1 && cc < 49) {
            const float* src = which ? refsr : lr;
            val = src[((size_t)(b * C3 + c)) * M48 + (rr - 1) * HW + (cc - 1)];
        }
    }
    float* dst = which ? g_rfp : g_lrp;
    dst[((size_t)(b * C3 + c)) * NPS + u] = val;
}

// ---------------- per-pixel channel sum of squares ----------------
__global__ void ssq_kernel() {
    int t = blockIdx.x * blockDim.x + threadIdx.x;
    if (t >= 2 * BATCH * NP) return;
    int u = t % NP; int b = (t / NP) & 1; int which = t / (BATCH * NP);
    const float* src = (which ? g_rfp : g_lrp) + (size_t)b * C3 * NPS + u;
    float acc = 0.f;
#pragma unroll 8
    for (int c = 0; c < C3; c++) { float x = src[(size_t)c * NPS]; acc += x * x; }
    g_SS[t] = acc;
}

// ---------------- patch inverse norms ----------------
__global__ void norm_kernel() {
    int t = blockIdx.x * blockDim.x + threadIdx.x;
    if (t >= 2 * BATCH * M48) return;
    int m = t % M48; int b = (t / M48) & 1; int which = t / (BATCH * M48);
    int mi = m / HW, mj = m % HW;
    const float* S = g_SS + (which * BATCH + b) * NP;
    float s = 0.f;
#pragma unroll
    for (int di = 0; di < 3; di++)
#pragma unroll
        for (int dj = 0; dj < 3; dj++)
            s += S[(mi + di) * HP + mj + dj];
    g_invn[t] = 1.0f / fmaxf(sqrtf(s), 1e-12f);
}

// ---------------- SGEMM: E = lrp^T * rfp (2560x2560, K=256), FFMA2, KTILE=32 ----------------
__device__ __forceinline__ void issue_tile(float* as, float* bs,
                                           const float* Aptr, const float* Bptr,
                                           int kt, int lk, int lc) {
#pragma unroll
    for (int r = 0; r < 4; r++) {
        uint32_t sa = (uint32_t)__cvta_generic_to_shared(as + (lk + 8 * r) * 128 + lc);
        const float* ga = Aptr + ((size_t)kt * KTILE + 8 * r) * NPS;
        asm volatile("cp.async.ca.shared.global [%0], [%1], 16;\n" :: "r"(sa), "l"(ga));
    }
#pragma unroll
    for (int r = 0; r < 4; r++) {
        uint32_t sb = (uint32_t)__cvta_generic_to_shared(bs + (lk + 8 * r) * 128 + lc);
        const float* gb = Bptr + ((size_t)kt * KTILE + 8 * r) * NPS;
        asm volatile("cp.async.ca.shared.global [%0], [%1], 16;\n" :: "r"(sb), "l"(gb));
    }
    asm volatile("cp.async.commit_group;\n" ::: "memory");
}

__global__ void __launch_bounds__(256) gemm_kernel() {
    int b = blockIdx.z;
    const float* A = g_lrp + (size_t)b * C3 * NPS;
    const float* B = g_rfp + (size_t)b * C3 * NPS;
    float* C = g_E + (size_t)b * NPS * NPS;

    extern __shared__ __align__(16) float smemf[];
    float* smA = smemf;                              // [STAGES][KTILE][128]
    float* smB = smemf + STAGES * KTILE * 128;

    int tid = threadIdx.x;
    int iBase = blockIdx.x * 128;
    int jBase = blockIdx.y * 128;
    int lk = tid >> 5;          // 0..7
    int lc = (tid & 31) << 2;   // 0..124
    const float* Aptr = A + (size_t)lk * NPS + iBase + lc;
    const float* Bptr = B + (size_t)lk * NPS + jBase + lc;

    issue_tile(smA + 0 * KTILE * 128, smB + 0 * KTILE * 128, Aptr, Bptr, 0, lk, lc);
    issue_tile(smA + 1 * KTILE * 128, smB + 1 * KTILE * 128, Aptr, Bptr, 1, lk, lc);

    int ty = tid >> 4, tx = tid & 15;   // 16x16 thread grid

    unsigned long long accp[8][4];
#pragma unroll
    for (int i = 0; i < 8; i++)
#pragma unroll
        for (int j = 0; j < 4; j++) accp[i][j] = 0ull;

    for (int kt = 0; kt < NKSTEPS; kt++) {
        asm volatile("cp.async.wait_group 1;\n" ::: "memory");
        __syncthreads();
        if (kt + 2 < NKSTEPS) {
            int st = (kt + 2) % STAGES;
            issue_tile(smA + st * KTILE * 128, smB + st * KTILE * 128, Aptr, Bptr, kt + 2, lk, lc);
        }
        int cur = kt % STAGES;
        const float* As = smA + cur * KTILE * 128;
        const float* Bs = smB + cur * KTILE * 128;
#pragma unroll
        for (int kk = 0; kk < KTILE; kk++) {
            float4 a0 = *(const float4*)&As[kk * 128 + ty * 4];
            float4 a1 = *(const float4*)&As[kk * 128 + 64 + ty * 4];
            unsigned long long bp[4];
            *(ulonglong2*)(bp)     = *(const ulonglong2*)&Bs[kk * 128 + tx * 4];
            *(ulonglong2*)(bp + 2) = *(const ulonglong2*)&Bs[kk * 128 + 64 + tx * 4];
            float ar[8] = {a0.x, a0.y, a0.z, a0.w, a1.x, a1.y, a1.z, a1.w};
#pragma unroll
            for (int i = 0; i < 8; i++) {
                unsigned long long a2;
                asm("mov.b64 %0, {%1, %1};" : "=l"(a2) : "r"(__float_as_uint(ar[i])));
#pragma unroll
                for (int jp = 0; jp < 4; jp++) {
                    asm("fma.rn.f32x2 %0, %1, %2, %0;"
                        : "+l"(accp[i][jp]) : "l"(a2), "l"(bp[jp]));
                }
            }
        }
    }

#pragma unroll
    for (int half = 0; half < 2; half++) {
#pragma unroll
        for (int ii = 0; ii < 4; ii++) {
            int i = half * 4 + ii;
            int row = iBase + half * 64 + ty * 4 + ii;
            float* crow = C + (size_t)row * NPS + jBase;
            *(ulonglong2*)(crow + tx * 4)      = make_ulonglong2(accp[i][0], accp[i][1]);
            *(ulonglong2*)(crow + 64 + tx * 4) = make_ulonglong2(accp[i][2], accp[i][3]);
        }
    }
}

// ---------------- aggregate 9 E-taps -> D row, plus argmax over keys ----------------
__global__ void __launch_bounds__(256) agg_kernel() {
    int m = blockIdx.x, b = blockIdx.y;
    int mi = m / HW, mj = m % HW;
    const float* Eb = g_E + (size_t)b * NPS * NPS;
    float inq = g_invn[(0 * BATCH + b) * M48 + m];
    const float* invk = g_invn + (1 * BATCH + b) * M48;
    float* Drow = g_D + ((size_t)b * M48 + m) * M48;

    const float* base0 = Eb + (size_t)((mi + 0) * HP + mj) * NPS + 0 * HP;
    const float* base1 = Eb + (size_t)((mi + 1) * HP + mj) * NPS + 1 * HP;
    const float* base2 = Eb + (size_t)((mi + 2) * HP + mj) * NPS + 2 * HP;

    float bv = -1e30f; int bi = 1 << 30;
    for (int l = threadIdx.x; l < M48; l += 256) {
        int li = l / HW, lj = l % HW;
        int o = li * HP + lj;
        float s = base0[o] + base0[o + NPS + 1] + base0[o + 2 * NPS + 2]
                + base1[o] + base1[o + NPS + 1] + base1[o + 2 * NPS + 2]
                + base2[o] + base2[o + NPS + 1] + base2[o + 2 * NPS + 2];
        float val = s * inq * invk[l];
        Drow[l] = val;
        if (val > bv) { bv = val; bi = l; }
    }
#pragma unroll
    for (int off = 16; off; off >>= 1) {
        float v2 = __shfl_down_sync(0xffffffffu, bv, off);
        int   i2 = __shfl_down_sync(0xffffffffu, bi, off);
        if (v2 > bv || (v2 == bv && i2 < bi)) { bv = v2; bi = i2; }
    }
    __shared__ float sv[8];
    __shared__ int   si[8];
    if ((threadIdx.x & 31) == 0) { sv[threadIdx.x >> 5] = bv; si[threadIdx.x >> 5] = bi; }
    __syncthreads();
    if (threadIdx.x == 0) {
        float v0 = sv[0]; int i0 = si[0];
#pragma unroll
        for (int w = 1; w < 8; w++) {
            if (sv[w] > v0 || (sv[w] == v0 && si[w] < i0)) { v0 = sv[w]; i0 = si[w]; }
        }
        g_Hidx[b * M48 + m] = i0;
    }
}

// ---------------- single-pass stable top-3 of D[m][Hidx[j]] over j ----------------
__device__ __forceinline__ void ins3(float v, int j,
                                     float& v0, int& i0, float& v1, int& i1, float& v2, int& i2) {
    bool b2 = (v > v2) || (v == v2 && j < i2);
    if (b2) {
        bool b1 = (v > v1) || (v == v1 && j < i1);
        if (b1) {
            bool b0 = (v > v0) || (v == v0 && j < i0);
            if (b0) { v2 = v1; i2 = i1; v1 = v0; i1 = i0; v0 = v; i0 = j; }
            else    { v2 = v1; i2 = i1; v1 = v;  i1 = j; }
        } else      { v2 = v;  i2 = j; }
    }
}

__global__ void __launch_bounds__(256) topk_kernel(float* __restrict__ outS) {
    int m = blockIdx.x, b = blockIdx.y;
    __shared__ float rowv[M48];
    __shared__ int   hs[M48];
    const float* Drow = g_D + ((size_t)b * M48 + m) * M48;
    for (int j = threadIdx.x; j < M48; j += 256) {
        rowv[j] = Drow[j];
        hs[j] = g_Hidx[b * M48 + j];
    }
    __syncthreads();

    float v0 = -1e30f, v1 = -1e30f, v2 = -1e30f;
    int   i0 = 1 << 30, i1 = 1 << 30, i2 = 1 << 30;
    for (int j = threadIdx.x; j < M48; j += 256) {
        ins3(rowv[hs[j]], j, v0, i0, v1, i1, v2, i2);
    }
#pragma unroll
    for (int off = 16; off; off >>= 1) {
        float w0 = __shfl_down_sync(0xffffffffu, v0, off);
        float w1 = __shfl_down_sync(0xffffffffu, v1, off);
        float w2 = __shfl_down_sync(0xffffffffu, v2, off);
        int   a0 = __shfl_down_sync(0xffffffffu, i0, off);
        int   a1 = __shfl_down_sync(0xffffffffu, i1, off);
        int   a2 = __shfl_down_sync(0xffffffffu, i2, off);
        ins3(w0, a0, v0, i0, v1, i1, v2, i2);
        ins3(w1, a1, v0, i0, v1, i1, v2, i2);
        ins3(w2, a2, v0, i0, v1, i1, v2, i2);
    }
    __shared__ float wv[8][3];
    __shared__ int   wi[8][3];
    if ((threadIdx.x & 31) == 0) {
        int w = threadIdx.x >> 5;
        wv[w][0] = v0; wv[w][1] = v1; wv[w][2] = v2;
        wi[w][0] = i0; wi[w][1] = i1; wi[w][2] = i2;
    }
    __syncthreads();
    if (threadIdx.x == 0) {
        float r0 = wv[0][0], r1 = wv[0][1], r2 = wv[0][2];
        int   s0 = wi[0][0], s1 = wi[0][1], s2 = wi[0][2];
#pragma unroll
        for (int w = 1; w < 8; w++) {
            ins3(wv[w][0], wi[w][0], r0, s0, r1, s1, r2, s2);
            ins3(wv[w][1], wi[w][1], r0, s0, r1, s1, r2, s2);
            ins3(wv[w][2], wi[w][2], r0, s0, r1, s1, r2, s2);
        }
        outS[(0 * BATCH + b) * M48 + m] = r0;
        outS[(1 * BATCH + b) * M48 + m] = r1;
        outS[(2 * BATCH + b) * M48 + m] = r2;
        g_src[(0 * BATCH + b) * M48 + m] = hs[s0];
        g_src[(1 * BATCH + b) * M48 + m] = hs[s1];
        g_src[(2 * BATCH + b) * M48 + m] = hs[s2];
    }
}

// ---------------- build per-pixel gather tables (9 offsets + weights) ----------------
__global__ void tbuild_kernel(int R, int S, int tabOfs, int npl) {
    int p = blockIdx.x * blockDim.x + threadIdx.x;
    if (p >= npl) return;
    int yx = p % (S * S); int ib = p / (S * S);
    int x = yx % S, y = yx / S;
    int b = ib & 1, i = ib >> 1;

    const int* srcTab = g_src + (i * BATCH + b) * M48;
    int yp = y + R, xp = x + R;
    int v = yp - 3 * R + 1; int milo = (v <= 0) ? 0 : (v + R - 1) / R;
    int mihi = yp / R; if (mihi > 47) mihi = 47;
    v = xp - 3 * R + 1; int mjlo = (v <= 0) ? 0 : (v + R - 1) / R;
    int mjhi = xp / R; if (mjhi > 47) mjhi = 47;

#pragma unroll
    for (int a = 0; a < 3; a++) {
        int mi = milo + a;
#pragma unroll
        for (int e = 0; e < 3; e++) {
            int mj = mjlo + e;
            int u = a * 3 + e;
            int off = 0; float w = 0.f;
            if (mi <= mihi && mj <= mjhi) {
                int s = srcTab[mi * HW + mj];
                int smi = s / HW, smj = s % HW;
                int ry = y + (smi - mi) * R;
                int rx = x + (smj - mj) * R;
                if (ry >= 0 && ry < S && rx >= 0 && rx < S) { off = ry * S + rx; w = 1.0f / 9.0f; }
            }
            g_toff[tabOfs + u * npl + p] = off;
            g_tw[tabOfs + u * npl + p] = w;
        }
    }
}

// ---------------- transfer: table-driven gather ----------------
__global__ void transfer_kernel(const float* __restrict__ ref, float* __restrict__ out,
                                int C, int S, int CCH, int tabOfs) {
    int t = blockIdx.x * blockDim.x + threadIdx.x;
    int nCh = C / CCH;
    int ss = S * S;
    if (t >= 6 * nCh * ss) return;
    int yx = t % ss; int r = t / ss;
    int cc = r % nCh; int ib = r / nCh;
    int npl = 6 * ss;
    int p = ib * ss + yx;

    int off[9]; float w[9];
#pragma unroll
    for (int u = 0; u < 9; u++) {
        off[u] = g_toff[tabOfs + u * npl + p];
        w[u]   = g_tw[tabOfs + u * npl + p];
    }

    int b = ib & 1, i = ib >> 1;
    int c0 = cc * CCH;
    const float* refb = ref + ((size_t)(b * C + c0)) * ss;
    float* outb = out + ((size_t)(i * BATCH + b) * C + c0) * ss + yx;
    for (int c = 0; c < CCH; c++) {
        const float* rc = refb + (size_t)c * ss;
        float acc = 0.f;
#pragma unroll
        for (int u = 0; u < 9; u++) acc = fmaf(w[u], __ldg(rc + off[u]), acc);
        outb[(size_t)c * ss] = acc;
    }
}

// ---------------- launch ----------------
extern "C" void kernel_launch(void* const* d_in, const int* in_sizes, int n_in,
                              void* d_out, int out_size) {
    const float* lr    = (const float*)d_in[0];
    const float* refsr = (const float*)d_in[1];
    const float* ref1  = (const float*)d_in[2];  // (2,64,192,192)
    const float* ref2  = (const float*)d_in[3];  // (2,128,96,96)
    const float* ref3  = (const float*)d_in[4];  // (2,256,48,48)
    float* out = (float*)d_out;

    float* outS  = out;
    float* outT3 = outS + 3 * BATCH * M48;
    float* outT2 = outT3 + 3 * BATCH * C3 * M48;
    float* outT1 = outT2 + 3 * BATCH * 128 * 96 * 96;

    {
        int n = 2 * BATCH * C3 * NPS;
        prep_kernel<<<(n + 255) / 256, 256>>>(lr, refsr);
    }
    ssq_kernel<<<(2 * BATCH * NP + 255) / 256, 256>>>();
    norm_kernel<<<(2 * BATCH * M48 + 255) / 256, 256>>>();

    cudaFuncSetAttribute(gemm_kernel, cudaFuncAttributeMaxDynamicSharedMemorySize, GEMM_SMEM);
    gemm_kernel<<<dim3(20, 20, BATCH), 256, GEMM_SMEM>>>();

    agg_kernel<<<dim3(M48, BATCH), 256>>>();
    topk_kernel<<<dim3(M48, BATCH), 256>>>(outS);

    tbuild_kernel<<<(NPL3 + 255) / 256, 256>>>(1, 48, TOFS3, NPL3);
    tbuild_kernel<<<(NPL2 + 255) / 256, 256>>>(2, 96, TOFS2, NPL2);
    tbuild_kernel<<<(NPL1 + 255) / 256, 256>>>(4, 192, TOFS1, NPL1);

    {   // lv3: C=256, S=48, CCH=16
        int n = 6 * (C3 / 16) * 48 * 48;
        transfer_kernel<<<(n + 255) / 256, 256>>>(ref3, outT3, 256, 48, 16, TOFS3);
    }
    {   // lv2: C=128, S=96, CCH=16
        int n = 6 * (128 / 16) * 96 * 96;
        transfer_kernel<<<(n + 255) / 256, 256>>>(ref2, outT2, 128, 96, 16, TOFS2);
    }
    {   // lv1: C=64, S=192, CCH=16
        int n = 6 * (64 / 16) * 192 * 192;
        transfer_kernel<<<(n + 255) / 256, 256>>>(ref1, outT1, 64, 192, 16, TOFS1);
    }
}

// round 7
// speedup vs baseline: 1.1525x; 1.0900x over previous
#include <cuda_runtime.h>
#include <cstdint>

// ---------------- problem constants ----------------
#define BATCH 2
#define C3 256
#define HW 48           // lv3 spatial
#define M48 (HW*HW)     // 2304 patch positions
#define HP 50           // padded 48+2
#define NP 2500         // 50*50
#define NPS 2560        // padded GEMM dim (20 * 128)
#define KTILE 32
#define NKSTEPS 8       // 256 / 32
#define STAGES 3
#define GEMM_SMEM (STAGES * KTILE * 128 * 2 * 4)   // 98304 bytes

// table sizes: plane-major per level, 9 planes of (6*S*S)
#define NPL3 (6 * 48 * 48)      // 13824
#define NPL2 (6 * 96 * 96)      // 55296
#define NPL1 (6 * 192 * 192)    // 221184
#define TOFS3 0
#define TOFS2 (9 * NPL3)
#define TOFS1 (TOFS2 + 9 * NPL2)
#define TTOT  (TOFS1 + 9 * NPL1)

// fused transfer thread counts (CCH = 16)
#define NT3 (6 * (256 / 16) * 48 * 48)     // 221184
#define NT2 (6 * (128 / 16) * 96 * 96)     // 442368
#define NT1 (6 * (64 / 16) * 192 * 192)    // 884736
#define NTALL (NT3 + NT2 + NT1)            // 1548288

// ---------------- scratch (device globals; no runtime alloc) ----------------
__device__ __align__(16) float g_lrp[BATCH * C3 * NPS];
__device__ __align__(16) float g_rfp[BATCH * C3 * NPS];
__device__ __align__(16) float g_E[(size_t)BATCH * NPS * NPS];
__device__ __align__(16) float g_D[(size_t)BATCH * M48 * M48];
__device__ float g_SS[2 * BATCH * NP];
__device__ float g_invn[2 * BATCH * M48];
__device__ int   g_Hidx[BATCH * M48];
__device__ int   g_src[3 * BATCH * M48];
__device__ int   g_toff[TTOT];     // packed: -1 = invalid tap

// ---------------- prep: zero-padded images ----------------
__global__ void prep_kernel(const float* __restrict__ lr, const float* __restrict__ refsr) {
    int t = blockIdx.x * blockDim.x + threadIdx.x;
    if (t >= 2 * BATCH * C3 * NPS) return;
    int u = t % NPS; int r = t / NPS;
    int c = r % C3; r /= C3;
    int b = r & 1; int which = r >> 1;
    float val = 0.f;
    if (u < NP) {
        int rr = u / HP, cc = u % HP;
        if (rr >= 1 && rr < 49 && cc >= 1 && cc < 49) {
            const float* src = which ? refsr : lr;
            val = src[((size_t)(b * C3 + c)) * M48 + (rr - 1) * HW + (cc - 1)];
        }
    }
    float* dst = which ? g_rfp : g_lrp;
    dst[((size_t)(b * C3 + c)) * NPS + u] = val;
}

// ---------------- per-pixel channel sum of squares ----------------
__global__ void ssq_kernel() {
    int t = blockIdx.x * blockDim.x + threadIdx.x;
    if (t >= 2 * BATCH * NP) return;
    int u = t % NP; int b = (t / NP) & 1; int which = t / (BATCH * NP);
    const float* src = (which ? g_rfp : g_lrp) + (size_t)b * C3 * NPS + u;
    float acc = 0.f;
#pragma unroll 8
    for (int c = 0; c < C3; c++) { float x = src[(size_t)c * NPS]; acc += x * x; }
    g_SS[t] = acc;
}

// ---------------- patch inverse norms ----------------
__global__ void norm_kernel() {
    int t = blockIdx.x * blockDim.x + threadIdx.x;
    if (t >= 2 * BATCH * M48) return;
    int m = t % M48; int b = (t / M48) & 1; int which = t / (BATCH * M48);
    int mi = m / HW, mj = m % HW;
    const float* S = g_SS + (which * BATCH + b) * NP;
    float s = 0.f;
#pragma unroll
    for (int di = 0; di < 3; di++)
#pragma unroll
        for (int dj = 0; dj < 3; dj++)
            s += S[(mi + di) * HP + mj + dj];
    g_invn[t] = 1.0f / fmaxf(sqrtf(s), 1e-12f);
}

// ---------------- SGEMM: E = lrp^T * rfp (2560x2560, K=256), FFMA2, KTILE=32 ----------------
__device__ __forceinline__ void issue_tile(float* as, float* bs,
                                           const float* Aptr, const float* Bptr,
                                           int kt, int lk, int lc) {
#pragma unroll
    for (int r = 0; r < 4; r++) {
        uint32_t sa = (uint32_t)__cvta_generic_to_shared(as + (lk + 8 * r) * 128 + lc);
        const float* ga = Aptr + ((size_t)kt * KTILE + 8 * r) * NPS;
        asm volatile("cp.async.ca.shared.global [%0], [%1], 16;\n" :: "r"(sa), "l"(ga));
    }
#pragma unroll
    for (int r = 0; r < 4; r++) {
        uint32_t sb = (uint32_t)__cvta_generic_to_shared(bs + (lk + 8 * r) * 128 + lc);
        const float* gb = Bptr + ((size_t)kt * KTILE + 8 * r) * NPS;
        asm volatile("cp.async.ca.shared.global [%0], [%1], 16;\n" :: "r"(sb), "l"(gb));
    }
    asm volatile("cp.async.commit_group;\n" ::: "memory");
}

__global__ void __launch_bounds__(256) gemm_kernel() {
    int b = blockIdx.z;
    const float* A = g_lrp + (size_t)b * C3 * NPS;
    const float* B = g_rfp + (size_t)b * C3 * NPS;
    float* C = g_E + (size_t)b * NPS * NPS;

    extern __shared__ __align__(16) float smemf[];
    float* smA = smemf;                              // [STAGES][KTILE][128]
    float* smB = smemf + STAGES * KTILE * 128;

    int tid = threadIdx.x;
    int iBase = blockIdx.x * 128;
    int jBase = blockIdx.y * 128;
    int lk = tid >> 5;          // 0..7
    int lc = (tid & 31) << 2;   // 0..124
    const float* Aptr = A + (size_t)lk * NPS + iBase + lc;
    const float* Bptr = B + (size_t)lk * NPS + jBase + lc;

    issue_tile(smA + 0 * KTILE * 128, smB + 0 * KTILE * 128, Aptr, Bptr, 0, lk, lc);
    issue_tile(smA + 1 * KTILE * 128, smB + 1 * KTILE * 128, Aptr, Bptr, 1, lk, lc);

    int ty = tid >> 4, tx = tid & 15;   // 16x16 thread grid

    unsigned long long accp[8][4];
#pragma unroll
    for (int i = 0; i < 8; i++)
#pragma unroll
        for (int j = 0; j < 4; j++) accp[i][j] = 0ull;

    for (int kt = 0; kt < NKSTEPS; kt++) {
        asm volatile("cp.async.wait_group 1;\n" ::: "memory");
        __syncthreads();
        if (kt + 2 < NKSTEPS) {
            int st = (kt + 2) % STAGES;
            issue_tile(smA + st * KTILE * 128, smB + st * KTILE * 128, Aptr, Bptr, kt + 2, lk, lc);
        }
        int cur = kt % STAGES;
        const float* As = smA + cur * KTILE * 128;
        const float* Bs = smB + cur * KTILE * 128;
#pragma unroll
        for (int kk = 0; kk < KTILE; kk++) {
            float4 a0 = *(const float4*)&As[kk * 128 + ty * 4];
            float4 a1 = *(const float4*)&As[kk * 128 + 64 + ty * 4];
            unsigned long long bp[4];
            *(ulonglong2*)(bp)     = *(const ulonglong2*)&Bs[kk * 128 + tx * 4];
            *(ulonglong2*)(bp + 2) = *(const ulonglong2*)&Bs[kk * 128 + 64 + tx * 4];
            float ar[8] = {a0.x, a0.y, a0.z, a0.w, a1.x, a1.y, a1.z, a1.w};
#pragma unroll
            for (int i = 0; i < 8; i++) {
                unsigned long long a2;
                asm("mov.b64 %0, {%1, %1};" : "=l"(a2) : "r"(__float_as_uint(ar[i])));
#pragma unroll
                for (int jp = 0; jp < 4; jp++) {
                    asm("fma.rn.f32x2 %0, %1, %2, %0;"
                        : "+l"(accp[i][jp]) : "l"(a2), "l"(bp[jp]));
                }
            }
        }
    }

#pragma unroll
    for (int half = 0; half < 2; half++) {
#pragma unroll
        for (int ii = 0; ii < 4; ii++) {
            int i = half * 4 + ii;
            int row = iBase + half * 64 + ty * 4 + ii;
            float* crow = C + (size_t)row * NPS + jBase;
            *(ulonglong2*)(crow + tx * 4)      = make_ulonglong2(accp[i][0], accp[i][1]);
            *(ulonglong2*)(crow + 64 + tx * 4) = make_ulonglong2(accp[i][2], accp[i][3]);
        }
    }
}

// ---------------- aggregate 9 E-taps -> D row, plus argmax over keys ----------------
__global__ void __launch_bounds__(256) agg_kernel() {
    int m = blockIdx.x, b = blockIdx.y;
    int mi = m / HW, mj = m % HW;
    const float* Eb = g_E + (size_t)b * NPS * NPS;
    float inq = g_invn[(0 * BATCH + b) * M48 + m];
    const float* invk = g_invn + (1 * BATCH + b) * M48;
    float* Drow = g_D + ((size_t)b * M48 + m) * M48;

    const float* base0 = Eb + (size_t)((mi + 0) * HP + mj) * NPS + 0 * HP;
    const float* base1 = Eb + (size_t)((mi + 1) * HP + mj) * NPS + 1 * HP;
    const float* base2 = Eb + (size_t)((mi + 2) * HP + mj) * NPS + 2 * HP;

    float bv = -1e30f; int bi = 1 << 30;
    for (int l = threadIdx.x; l < M48; l += 256) {
        int li = l / HW, lj = l % HW;
        int o = li * HP + lj;
        float s = base0[o] + base0[o + NPS + 1] + base0[o + 2 * NPS + 2]
                + base1[o] + base1[o + NPS + 1] + base1[o + 2 * NPS + 2]
                + base2[o] + base2[o + NPS + 1] + base2[o + 2 * NPS + 2];
        float val = s * inq * invk[l];
        Drow[l] = val;
        if (val > bv) { bv = val; bi = l; }
    }
#pragma unroll
    for (int off = 16; off; off >>= 1) {
        float v2 = __shfl_down_sync(0xffffffffu, bv, off);
        int   i2 = __shfl_down_sync(0xffffffffu, bi, off);
        if (v2 > bv || (v2 == bv && i2 < bi)) { bv = v2; bi = i2; }
    }
    __shared__ float sv[8];
    __shared__ int   si[8];
    if ((threadIdx.x & 31) == 0) { sv[threadIdx.x >> 5] = bv; si[threadIdx.x >> 5] = bi; }
    __syncthreads();
    if (threadIdx.x == 0) {
        float v0 = sv[0]; int i0 = si[0];
#pragma unroll
        for (int w = 1; w < 8; w++) {
            if (sv[w] > v0 || (sv[w] == v0 && si[w] < i0)) { v0 = sv[w]; i0 = si[w]; }
        }
        g_Hidx[b * M48 + m] = i0;
    }
}

// ---------------- single-pass stable top-3 of D[m][Hidx[j]] over j ----------------
__device__ __forceinline__ void ins3(float v, int j,
                                     float& v0, int& i0, float& v1, int& i1, float& v2, int& i2) {
    bool b2 = (v > v2) || (v == v2 && j < i2);
    if (b2) {
        bool b1 = (v > v1) || (v == v1 && j < i1);
        if (b1) {
            bool b0 = (v > v0) || (v == v0 && j < i0);
            if (b0) { v2 = v1; i2 = i1; v1 = v0; i1 = i0; v0 = v; i0 = j; }
            else    { v2 = v1; i2 = i1; v1 = v;  i1 = j; }
        } else      { v2 = v;  i2 = j; }
    }
}

__global__ void __launch_bounds__(256) topk_kernel(float* __restrict__ outS) {
    int m = blockIdx.x, b = blockIdx.y;
    __shared__ float rowv[M48];
    __shared__ int   hs[M48];
    const float* Drow = g_D + ((size_t)b * M48 + m) * M48;
    for (int j = threadIdx.x; j < M48; j += 256) {
        rowv[j] = Drow[j];
        hs[j] = g_Hidx[b * M48 + j];
    }
    __syncthreads();

    float v0 = -1e30f, v1 = -1e30f, v2 = -1e30f;
    int   i0 = 1 << 30, i1 = 1 << 30, i2 = 1 << 30;
    for (int j = threadIdx.x; j < M48; j += 256) {
        ins3(rowv[hs[j]], j, v0, i0, v1, i1, v2, i2);
    }
#pragma unroll
    for (int off = 16; off; off >>= 1) {
        float w0 = __shfl_down_sync(0xffffffffu, v0, off);
        float w1 = __shfl_down_sync(0xffffffffu, v1, off);
        float w2 = __shfl_down_sync(0xffffffffu, v2, off);
        int   a0 = __shfl_down_sync(0xffffffffu, i0, off);
        int   a1 = __shfl_down_sync(0xffffffffu, i1, off);
        int   a2 = __shfl_down_sync(0xffffffffu, i2, off);
        ins3(w0, a0, v0, i0, v1, i1, v2, i2);
        ins3(w1, a1, v0, i0, v1, i1, v2, i2);
        ins3(w2, a2, v0, i0, v1, i1, v2, i2);
    }
    __shared__ float wv[8][3];
    __shared__ int   wi[8][3];
    if ((threadIdx.x & 31) == 0) {
        int w = threadIdx.x >> 5;
        wv[w][0] = v0; wv[w][1] = v1; wv[w][2] = v2;
        wi[w][0] = i0; wi[w][1] = i1; wi[w][2] = i2;
    }
    __syncthreads();
    if (threadIdx.x == 0) {
        float r0 = wv[0][0], r1 = wv[0][1], r2 = wv[0][2];
        int   s0 = wi[0][0], s1 = wi[0][1], s2 = wi[0][2];
#pragma unroll
        for (int w = 1; w < 8; w++) {
            ins3(wv[w][0], wi[w][0], r0, s0, r1, s1, r2, s2);
            ins3(wv[w][1], wi[w][1], r0, s0, r1, s1, r2, s2);
            ins3(wv[w][2], wi[w][2], r0, s0, r1, s1, r2, s2);
        }
        outS[(0 * BATCH + b) * M48 + m] = r0;
        outS[(1 * BATCH + b) * M48 + m] = r1;
        outS[(2 * BATCH + b) * M48 + m] = r2;
        g_src[(0 * BATCH + b) * M48 + m] = hs[s0];
        g_src[(1 * BATCH + b) * M48 + m] = hs[s1];
        g_src[(2 * BATCH + b) * M48 + m] = hs[s2];
    }
}

// ---------------- build per-pixel packed gather tables (9 offsets, -1 = invalid) --------
__device__ __forceinline__ void tbuild_one(int R, int S, int tabOfs, int npl, int p) {
    int yx = p % (S * S); int ib = p / (S * S);
    int x = yx % S, y = yx / S;
    int b = ib & 1, i = ib >> 1;

    const int* srcTab = g_src + (i * BATCH + b) * M48;
    int yp = y + R, xp = x + R;
    int v = yp - 3 * R + 1; int milo = (v <= 0) ? 0 : (v + R - 1) / R;
    int mihi = yp / R; if (mihi > 47) mihi = 47;
    v = xp - 3 * R + 1; int mjlo = (v <= 0) ? 0 : (v + R - 1) / R;
    int mjhi = xp / R; if (mjhi > 47) mjhi = 47;

#pragma unroll
    for (int a = 0; a < 3; a++) {
        int mi = milo + a;
#pragma unroll
        for (int e = 0; e < 3; e++) {
            int mj = mjlo + e;
            int u = a * 3 + e;
            int off = -1;
            if (mi <= mihi && mj <= mjhi) {
                int s = srcTab[mi * HW + mj];
                int smi = s / HW, smj = s % HW;
                int ry = y + (smi - mi) * R;
                int rx = x + (smj - mj) * R;
                if (ry >= 0 && ry < S && rx >= 0 && rx < S) off = ry * S + rx;
            }
            g_toff[tabOfs + u * npl + p] = off;
        }
    }
}

__global__ void tbuild_all_kernel() {
    int t = blockIdx.x * blockDim.x + threadIdx.x;
    if (t < NPL3)               tbuild_one(1, 48,  TOFS3, NPL3, t);
    else if (t < NPL3 + NPL2)   tbuild_one(2, 96,  TOFS2, NPL2, t - NPL3);
    else if (t < NPL3 + NPL2 + NPL1) tbuild_one(4, 192, TOFS1, NPL1, t - NPL3 - NPL2);
}

// ---------------- fused transfer: table-driven gather, all 3 levels ----------------
__device__ __forceinline__ void transfer_one(const float* __restrict__ ref,
                                             float* __restrict__ out,
                                             int C, int S, int tabOfs, int t) {
    int ss = S * S;
    int nCh = C / 16;
    int yx = t % ss; int r = t / ss;
    int cc = r % nCh; int ib = r / nCh;
    int npl = 6 * ss;
    int p = ib * ss + yx;

    int off[9];
#pragma unroll
    for (int u = 0; u < 9; u++) off[u] = g_toff[tabOfs + u * npl + p];

    int b = ib & 1, i = ib >> 1;
    const float* refb = ref + ((size_t)(b * C + cc * 16)) * ss;
    float* outb = out + ((size_t)(i * BATCH + b) * C + cc * 16) * ss + yx;
#pragma unroll
    for (int c = 0; c < 16; c++) {
        const float* rc = refb + (size_t)c * ss;
        float acc = 0.f;
#pragma unroll
        for (int u = 0; u < 9; u++) {
            int o = off[u];
            if (o >= 0) acc += __ldg(rc + o);
        }
        outb[(size_t)c * ss] = acc * (1.0f / 9.0f);
    }
}

__global__ void transfer_all_kernel(const float* __restrict__ ref3, float* __restrict__ out3,
                                    const float* __restrict__ ref2, float* __restrict__ out2,
                                    const float* __restrict__ ref1, float* __restrict__ out1) {
    int t = blockIdx.x * blockDim.x + threadIdx.x;
    if (t < NT3)            transfer_one(ref3, out3, 256, 48,  TOFS3, t);
    else if (t < NT3 + NT2) transfer_one(ref2, out2, 128, 96,  TOFS2, t - NT3);
    else                    transfer_one(ref1, out1, 64,  192, TOFS1, t - NT3 - NT2);
}

// ---------------- launch ----------------
extern "C" void kernel_launch(void* const* d_in, const int* in_sizes, int n_in,
                              void* d_out, int out_size) {
    const float* lr    = (const float*)d_in[0];
    const float* refsr = (const float*)d_in[1];
    const float* ref1  = (const float*)d_in[2];  // (2,64,192,192)
    const float* ref2  = (const float*)d_in[3];  // (2,128,96,96)
    const float* ref3  = (const float*)d_in[4];  // (2,256,48,48)
    float* out = (float*)d_out;

    float* outS  = out;
    float* outT3 = outS + 3 * BATCH * M48;
    float* outT2 = outT3 + 3 * BATCH * C3 * M48;
    float* outT1 = outT2 + 3 * BATCH * 128 * 96 * 96;

    {
        int n = 2 * BATCH * C3 * NPS;
        prep_kernel<<<(n + 255) / 256, 256>>>(lr, refsr);
    }
    ssq_kernel<<<(2 * BATCH * NP + 255) / 256, 256>>>();
    norm_kernel<<<(2 * BATCH * M48 + 255) / 256, 256>>>();

    cudaFuncSetAttribute(gemm_kernel, cudaFuncAttributeMaxDynamicSharedMemorySize, GEMM_SMEM);
    gemm_kernel<<<dim3(20, 20, BATCH), 256, GEMM_SMEM>>>();

    agg_kernel<<<dim3(M48, BATCH), 256>>>();
    topk_kernel<<<dim3(M48, BATCH), 256>>>(outS);

    {
        int n = NPL3 + NPL2 + NPL1;
        tbuild_all_kernel<<<(n + 255) / 256, 256>>>();
    }
    transfer_all_kernel<<<NTALL / 256, 256>>>(ref3, outT3, ref2, outT2, ref1, outT1);
}